// round 3
// baseline (speedup 1.0000x reference)
#include <cuda_runtime.h>
#include <math.h>

#define MAXBLK 4096

__device__ __align__(16) float g_Acoef[81 * 4];     // [m][ow]
__device__ __align__(16) float g_part[MAXBLK * 8];  // per-block partial sums
__device__ __align__(16) float g_norm[8];           // scale[4], bias[4]
__device__ int g_counter;
__device__ int g_flag;

struct C2 { float re, im; };

// ---------------------------------------------------------------------------
// Setup: build the 4x81 multilinear coefficient table from weights (on device,
// every launch -> deterministic + graph-capturable). Also resets sync state.
// ---------------------------------------------------------------------------
__global__ void setup_kernel(const float* __restrict__ W)  // [2][4][3]
{
    __shared__ C2 M[16][16];
    __shared__ float G[4][16][16];
    int tid = threadIdx.x;

    if (tid == 0) { g_counter = 0; g_flag = 0; }

    if (tid < 16) {
        int j = tid;
        C2 st[16];
#pragma unroll
        for (int i = 0; i < 16; i++) { st[i].re = (i == j) ? 1.f : 0.f; st[i].im = 0.f; }

#pragma unroll
        for (int l = 0; l < 2; l++) {
#pragma unroll
            for (int w = 0; w < 4; w++) {
                float ax = W[(l * 4 + w) * 3 + 0] * 0.5f;
                float ay = W[(l * 4 + w) * 3 + 1] * 0.5f;
                float az = W[(l * 4 + w) * 3 + 2] * 0.5f;
                const int mask = 1 << (3 - w);
                {   // RX
                    float c = cosf(ax), s = sinf(ax);
#pragma unroll
                    for (int i = 0; i < 16; i++) {
                        if (i & mask) continue;
                        C2 a = st[i], b = st[i | mask];
                        st[i]        = { c * a.re + s * b.im,  c * a.im - s * b.re };
                        st[i | mask] = { s * a.im + c * b.re, -s * a.re + c * b.im };
                    }
                }
                {   // RY
                    float c = cosf(ay), s = sinf(ay);
#pragma unroll
                    for (int i = 0; i < 16; i++) {
                        if (i & mask) continue;
                        C2 a = st[i], b = st[i | mask];
                        st[i]        = { c * a.re - s * b.re, c * a.im - s * b.im };
                        st[i | mask] = { s * a.re + c * b.re, s * a.im + c * b.im };
                    }
                }
                {   // RZ
                    float c = cosf(az), s = sinf(az);
#pragma unroll
                    for (int i = 0; i < 16; i++) {
                        C2 a = st[i];
                        if (i & mask) st[i] = { c * a.re - s * a.im, c * a.im + s * a.re };
                        else          st[i] = { c * a.re + s * a.im, c * a.im - s * a.re };
                    }
                }
            }
#pragma unroll
            for (int w = 0; w < 4; w++) {     // CNOT ring
                int t = (w + 1) & 3;
                int cm = 1 << (3 - w), tm = 1 << (3 - t);
                C2 tmp[16];
#pragma unroll
                for (int i = 0; i < 16; i++) tmp[i] = st[(i & cm) ? (i ^ tm) : i];
#pragma unroll
                for (int i = 0; i < 16; i++) st[i] = tmp[i];
            }
        }
#pragma unroll
        for (int i = 0; i < 16; i++) M[i][j] = st[i];
    }
    __syncthreads();

    {   // G_ow[j][k] = Re( i^(pc(j)-pc(k)) * sum_i sign_ow(i) conj(M[i][j]) M[i][k] )
        int ow = tid >> 8;
        int j = (tid >> 4) & 15;
        int k = tid & 15;
        float hr = 0.f, hi = 0.f;
#pragma unroll
        for (int i = 0; i < 16; i++) {
            float sgn = ((i >> (3 - ow)) & 1) ? -1.f : 1.f;
            C2 a = M[i][j], b = M[i][k];
            hr += sgn * (a.re * b.re + a.im * b.im);
            hi += sgn * (a.re * b.im - a.im * b.re);
        }
        int ph = (__popc(j) - __popc(k)) & 3;
        float g = (ph == 0) ? hr : (ph == 1) ? -hi : (ph == 2) ? -hr : hi;
        G[ow][j][k] = g;
    }
    __syncthreads();

    if (tid < 324) {   // multilinear coefficients
        int ow = tid / 81;
        int m = tid % 81;
        int md[4] = { m / 27, (m / 9) % 3, (m / 3) % 3, m % 3 };
        float acc = 0.f;
#pragma unroll
        for (int t = 0; t < 16; t++) {
            int j = 0, k = 0;
            float sgn = 1.f;
#pragma unroll
            for (int w = 0; w < 4; w++) {
                int tb = (t >> (3 - w)) & 1;
                int jb, kb;
                if (md[w] == 2) { jb = tb; kb = 1 - tb; }
                else { jb = tb; kb = tb; if (md[w] == 1 && tb == 1) sgn = -sgn; }
                j |= jb << (3 - w);
                k |= kb << (3 - w);
            }
            acc += sgn * G[ow][j][k];
        }
        g_Acoef[m * 4 + ow] = acc * (1.f / 16.f);
    }
}

// ---------------------------------------------------------------------------
// Fused persistent kernel: pool + circuit + reduce + batchnorm + output.
// q never touches global memory (register-resident across the grid sync).
// ---------------------------------------------------------------------------
__global__ __launch_bounds__(256, 2)
void fused_kernel(const float* __restrict__ x,
                  const float* __restrict__ gamma,
                  const float* __restrict__ beta,
                  float* __restrict__ out,
                  int B, int nChunks)
{
    __shared__ float4 As[81];
    __shared__ float wsum[8][8];
    __shared__ int isLast;
    __shared__ double red[8][32];
    __shared__ double tot[8];

    int tid = threadIdx.x;
    if (tid < 81) As[tid] = ((const float4*)g_Acoef)[tid];

    int lane = tid & 31;
    int w = tid >> 5;
    int gw = blockIdx.x * 8 + w;
    int totalWarps = gridDim.x * 8;

    // Per-lane constant wire classification (2x6x6 average pool on 12x12).
    int p0 = lane * 4;
    int rb0 = (p0 >= 72) ? 2 : 0;
    int off0 = p0 % 12;
    int wA0 = rb0 + (off0 == 8);
    int wB0 = rb0 + (off0 >= 4);
    int p1 = 128 + lane * 4;
    int off1 = p1 % 12;
    int wA1 = (lane < 4) ? (2 + (off1 == 8)) : -1;
    int wB1 = (lane < 4) ? (2 + (off1 >= 4)) : -1;

    float mA00 = (wA0 == 0), mA01 = (wA0 == 1), mA02 = (wA0 == 2), mA03 = (wA0 == 3);
    float mB00 = (wB0 == 0), mB01 = (wB0 == 1), mB02 = (wB0 == 2), mB03 = (wB0 == 3);
    float mA12 = (wA1 == 2), mA13 = (wA1 == 3);
    float mB12 = (wB1 == 2), mB13 = (wB1 == 3);

    const float4* xb = (const float4*)x;
    float s[8] = { 0, 0, 0, 0, 0, 0, 0, 0 };
    float4 qv[2];
    int bases[2];

    __syncthreads();   // As ready

#pragma unroll
    for (int cc = 0; cc < 2; cc++) {
        int chunk = gw + cc * totalWarps;
        bases[cc] = -1;
        qv[cc] = make_float4(0.f, 0.f, 0.f, 0.f);
        if (chunk >= nChunks) continue;
        int base = chunk * 32;
        bases[cc] = base;

        float4 keep = make_float4(0.f, 0.f, 0.f, 0.f);
#pragma unroll 8
        for (int it = 0; it < 32; it++) {
            int item = base + it;
            float4 v0 = make_float4(0.f, 0.f, 0.f, 0.f);
            float4 v1 = make_float4(0.f, 0.f, 0.f, 0.f);
            if (item < B) {
                const float4* p = xb + (size_t)item * 36;
                v0 = p[lane];
                if (lane < 4) v1 = p[32 + lane];
            }
            float sA0 = v0.x + v0.y, sB0 = v0.z + v0.w;
            float sA1 = v1.x + v1.y, sB1 = v1.z + v1.w;

            float a0 = mA00 * sA0 + mB00 * sB0;
            float a1 = mA01 * sA0 + mB01 * sB0;
            float a2 = mA02 * sA0 + mB02 * sB0 + mA12 * sA1 + mB12 * sB1;
            float a3 = mA03 * sA0 + mB03 * sB0 + mA13 * sA1 + mB13 * sB1;

#pragma unroll
            for (int sh = 16; sh; sh >>= 1) {
                a0 += __shfl_xor_sync(0xffffffffu, a0, sh);
                a1 += __shfl_xor_sync(0xffffffffu, a1, sh);
                a2 += __shfl_xor_sync(0xffffffffu, a2, sh);
                a3 += __shfl_xor_sync(0xffffffffu, a3, sh);
            }
            keep.x = (lane == it) ? a0 : keep.x;
            keep.y = (lane == it) ? a1 : keep.y;
            keep.z = (lane == it) ? a2 : keep.z;
            keep.w = (lane == it) ? a3 : keep.w;
        }

        int item = base + lane;
        if (item < B) {
            const float inv = 1.f / 36.f;
            float c0, s0, c1, s1, c2, s2, c3, s3;
            __sincosf(keep.x * inv, &s0, &c0);
            __sincosf(keep.y * inv, &s1, &c1);
            __sincosf(keep.z * inv, &s2, &c2);
            __sincosf(keep.w * inv, &s3, &c3);

            float t01[9] = { 1.f, c1, s1, c0, c0 * c1, c0 * s1, s0, s0 * c1, s0 * s1 };
            float t23[9] = { 1.f, c3, s3, c2, c2 * c3, c2 * s3, s2, s2 * c3, s2 * s3 };

            float q0 = 0.f, q1 = 0.f, q2 = 0.f, q3 = 0.f;
#pragma unroll
            for (int m = 0; m < 81; m++) {
                float bs = t01[m / 9] * t23[m % 9];
                float4 a = As[m];
                q0 = fmaf(a.x, bs, q0);
                q1 = fmaf(a.y, bs, q1);
                q2 = fmaf(a.z, bs, q2);
                q3 = fmaf(a.w, bs, q3);
            }
            qv[cc] = make_float4(q0, q1, q2, q3);
            s[0] += q0; s[1] += q1; s[2] += q2; s[3] += q3;
            s[4] += q0 * q0; s[5] += q1 * q1; s[6] += q2 * q2; s[7] += q3 * q3;
        }
    }

    // Block reduce the 8 partial sums.
#pragma unroll
    for (int sh = 16; sh; sh >>= 1)
#pragma unroll
        for (int k = 0; k < 8; k++) s[k] += __shfl_xor_sync(0xffffffffu, s[k], sh);
    if (lane == 0) {
#pragma unroll
        for (int k = 0; k < 8; k++) wsum[w][k] = s[k];
    }
    __syncthreads();
    if (tid < 8) {
        float acc = 0.f;
#pragma unroll
        for (int ww = 0; ww < 8; ww++) acc += wsum[ww][tid];
        g_part[blockIdx.x * 8 + tid] = acc;
        __threadfence();
    }
    __syncthreads();
    if (tid == 0) {
        unsigned pos = atomicAdd(&g_counter, 1);
        isLast = (pos == gridDim.x - 1);
    }
    __syncthreads();

    if (isLast) {
        __threadfence();
        int k = tid & 7;
        int slice = tid >> 3;
        double acc = 0.0;
        for (int b = slice; b < (int)gridDim.x; b += 32)
            acc += (double)g_part[b * 8 + k];
        red[k][slice] = acc;
        __syncthreads();
        if (tid < 8) {
            double t = 0.0;
#pragma unroll
            for (int i = 0; i < 32; i++) t += red[tid][i];
            tot[tid] = t;
        }
        __syncthreads();
        if (tid < 4) {
            double mean = tot[tid] / (double)B;
            double var = tot[4 + tid] / (double)B - mean * mean;
            float scale = gamma[tid] * rsqrtf((float)var + 1e-5f);
            g_norm[tid] = scale;
            g_norm[4 + tid] = beta[tid] - (float)mean * scale;
            __threadfence();
        }
        __syncthreads();
        if (tid == 0) atomicExch(&g_flag, 1);
    }

    // Grid-wide spin: wait for norm params.
    if (tid == 0) {
        while (*(volatile int*)&g_flag == 0) __nanosleep(64);
    }
    __syncthreads();
    __threadfence();

    float sc0 = __ldcg(&g_norm[0]), sc1 = __ldcg(&g_norm[1]);
    float sc2 = __ldcg(&g_norm[2]), sc3 = __ldcg(&g_norm[3]);
    float bs0 = __ldcg(&g_norm[4]), bs1 = __ldcg(&g_norm[5]);
    float bs2 = __ldcg(&g_norm[6]), bs3 = __ldcg(&g_norm[7]);

#pragma unroll
    for (int cc = 0; cc < 2; cc++) {
        if (bases[cc] < 0) continue;
        int item = bases[cc] + lane;
        if (item < B) {
            float4 o;
            o.x = fmaf(qv[cc].x, sc0, bs0);
            o.y = fmaf(qv[cc].y, sc1, bs1);
            o.z = fmaf(qv[cc].z, sc2, bs2);
            o.w = fmaf(qv[cc].w, sc3, bs3);
            ((float4*)out)[item] = o;
        }
    }
}

// ---------------------------------------------------------------------------
extern "C" void kernel_launch(void* const* d_in, const int* in_sizes, int n_in,
                              void* d_out, int out_size)
{
    const float* x     = (const float*)d_in[0];
    const float* W     = (const float*)d_in[1];
    const float* gamma = (const float*)d_in[2];
    const float* beta  = (const float*)d_in[3];
    float* out = (float*)d_out;

    int B = in_sizes[0] / 144;
    int nChunks = (B + 31) / 32;

    // Grid: 2 blocks/SM, all co-resident (needed for the spin sync).
    int nb = 296;
    // Each warp covers up to 2 chunks of 32 items; ensure coverage.
    while (nb * 8 * 2 < nChunks && nb < MAXBLK) nb += 296;

    setup_kernel<<<1, 1024>>>(W);
    fused_kernel<<<nb, 256>>>(x, gamma, beta, out, B, nChunks);
}

// round 4
// speedup vs baseline: 1.2384x; 1.2384x over previous
#include <cuda_runtime.h>
#include <math.h>

#define MAXBLK 4096

__device__ __align__(16) float g_Acoef[81 * 4];     // [m][ow]
__device__ __align__(16) float g_q[(1 << 17) * 4];  // q per item
__device__ __align__(16) float g_part[MAXBLK * 8];  // per-block partial sums

struct C2 { float re, im; };

// ---------------------------------------------------------------------------
// Setup: build the 4x81 multilinear coefficient table from weights.
// ---------------------------------------------------------------------------
__global__ void setup_kernel(const float* __restrict__ W)  // [2][4][3]
{
    __shared__ C2 M[16][16];
    __shared__ float G[4][16][16];
    int tid = threadIdx.x;

    if (tid < 16) {
        int j = tid;
        C2 st[16];
#pragma unroll
        for (int i = 0; i < 16; i++) { st[i].re = (i == j) ? 1.f : 0.f; st[i].im = 0.f; }

#pragma unroll
        for (int l = 0; l < 2; l++) {
#pragma unroll
            for (int w = 0; w < 4; w++) {
                float ax = W[(l * 4 + w) * 3 + 0] * 0.5f;
                float ay = W[(l * 4 + w) * 3 + 1] * 0.5f;
                float az = W[(l * 4 + w) * 3 + 2] * 0.5f;
                const int mask = 1 << (3 - w);
                {   // RX
                    float c = cosf(ax), s = sinf(ax);
#pragma unroll
                    for (int i = 0; i < 16; i++) {
                        if (i & mask) continue;
                        C2 a = st[i], b = st[i | mask];
                        st[i]        = { c * a.re + s * b.im,  c * a.im - s * b.re };
                        st[i | mask] = { s * a.im + c * b.re, -s * a.re + c * b.im };
                    }
                }
                {   // RY
                    float c = cosf(ay), s = sinf(ay);
#pragma unroll
                    for (int i = 0; i < 16; i++) {
                        if (i & mask) continue;
                        C2 a = st[i], b = st[i | mask];
                        st[i]        = { c * a.re - s * b.re, c * a.im - s * b.im };
                        st[i | mask] = { s * a.re + c * b.re, s * a.im + c * b.im };
                    }
                }
                {   // RZ
                    float c = cosf(az), s = sinf(az);
#pragma unroll
                    for (int i = 0; i < 16; i++) {
                        C2 a = st[i];
                        if (i & mask) st[i] = { c * a.re - s * a.im, c * a.im + s * a.re };
                        else          st[i] = { c * a.re + s * a.im, c * a.im - s * a.re };
                    }
                }
            }
#pragma unroll
            for (int w = 0; w < 4; w++) {     // CNOT ring
                int t = (w + 1) & 3;
                int cm = 1 << (3 - w), tm = 1 << (3 - t);
                C2 tmp[16];
#pragma unroll
                for (int i = 0; i < 16; i++) tmp[i] = st[(i & cm) ? (i ^ tm) : i];
#pragma unroll
                for (int i = 0; i < 16; i++) st[i] = tmp[i];
            }
        }
#pragma unroll
        for (int i = 0; i < 16; i++) M[i][j] = st[i];
    }
    __syncthreads();

    {   // G_ow[j][k]
        int ow = tid >> 8;
        int j = (tid >> 4) & 15;
        int k = tid & 15;
        float hr = 0.f, hi = 0.f;
#pragma unroll
        for (int i = 0; i < 16; i++) {
            float sgn = ((i >> (3 - ow)) & 1) ? -1.f : 1.f;
            C2 a = M[i][j], b = M[i][k];
            hr += sgn * (a.re * b.re + a.im * b.im);
            hi += sgn * (a.re * b.im - a.im * b.re);
        }
        int ph = (__popc(j) - __popc(k)) & 3;
        float g = (ph == 0) ? hr : (ph == 1) ? -hi : (ph == 2) ? -hr : hi;
        G[ow][j][k] = g;
    }
    __syncthreads();

    if (tid < 324) {   // multilinear coefficients
        int ow = tid / 81;
        int m = tid % 81;
        int md[4] = { m / 27, (m / 9) % 3, (m / 3) % 3, m % 3 };
        float acc = 0.f;
#pragma unroll
        for (int t = 0; t < 16; t++) {
            int j = 0, k = 0;
            float sgn = 1.f;
#pragma unroll
            for (int w = 0; w < 4; w++) {
                int tb = (t >> (3 - w)) & 1;
                int jb, kb;
                if (md[w] == 2) { jb = tb; kb = 1 - tb; }
                else { jb = tb; kb = tb; if (md[w] == 1 && tb == 1) sgn = -sgn; }
                j |= jb << (3 - w);
                k |= kb << (3 - w);
            }
            acc += sgn * G[ow][j][k];
        }
        g_Acoef[m * 4 + ow] = acc * (1.f / 16.f);
    }
}

// ---------------------------------------------------------------------------
// Main: pool (smem transpose, ~1 SHFL/item) + circuit + per-block partials.
// Block handles 256 items as 4 subtiles of 64.
// ---------------------------------------------------------------------------
__global__ __launch_bounds__(256, 3)
void main_kernel(const float* __restrict__ x, int B)
{
    __shared__ float4 tile[64 * 36];      // 36,864 B
    __shared__ float4 As[81];
    __shared__ float wsum[8][8];

    int tid = threadIdx.x;
    int lane = tid & 31;
    int w = tid >> 5;
    if (tid < 81) As[tid] = ((const float4*)g_Acoef)[tid];

    int blockBase = blockIdx.x * 256;
    const float4* x4 = (const float4*)x;
    long totalF4 = (long)B * 36;

    int g = lane >> 2;           // item group within warp-subtile (0..7)
    int q = lane & 3;            // quarter
    int rdBase = (w * 8 + g) * 36 + q * 9;
    int myT = lane >> 3;         // which subtile this lane's item comes from
    int srcLane = (lane & 7) * 4;

    float a0 = 0.f, a1 = 0.f, a2 = 0.f, a3 = 0.f;

#pragma unroll
    for (int t = 0; t < 4; t++) {
        long gBase = (long)(blockBase + t * 64) * 36;
        // Coalesced load of subtile into smem.
#pragma unroll
        for (int k = 0; k < 9; k++) {
            long gi = gBase + tid + k * 256;
            float4 v = make_float4(0.f, 0.f, 0.f, 0.f);
            if (gi < totalF4) v = x4[gi];
            tile[tid + k * 256] = v;
        }
        __syncthreads();

        // Per-thread: sum 9 float4 of quarter q of item (w*8+g).
        // Column class is i%3 (compile-time); row half is constant per thread.
        float r0 = 0.f, r1 = 0.f;
#pragma unroll
        for (int i = 0; i < 9; i++) {
            float4 v = tile[rdBase + i];
            float sA = v.x + v.y;
            float sB = v.z + v.w;
            if (i % 3 == 0)      r0 += sA + sB;
            else if (i % 3 == 1) { r0 += sA; r1 += sB; }
            else                 r1 += sA + sB;
        }
        __syncthreads();

        // Combine quarters: xor1 merges (q0,q1) and (q2,q3); xor2 swaps halves.
        r0 += __shfl_xor_sync(0xffffffffu, r0, 1);
        r1 += __shfl_xor_sync(0xffffffffu, r1, 1);
        float r2 = __shfl_xor_sync(0xffffffffu, r0, 2);
        float r3 = __shfl_xor_sync(0xffffffffu, r1, 2);
        // Lanes with q<2 now hold (w0,w1,w2,w3) in (r0,r1,r2,r3).

        // Gather: lane owns item (myT subtile, group lane&7) -> src lane 4*(lane&7).
        float b0 = __shfl_sync(0xffffffffu, r0, srcLane);
        float b1 = __shfl_sync(0xffffffffu, r1, srcLane);
        float b2 = __shfl_sync(0xffffffffu, r2, srcLane);
        float b3 = __shfl_sync(0xffffffffu, r3, srcLane);
        bool mine = (myT == t);
        a0 = mine ? b0 : a0;
        a1 = mine ? b1 : a1;
        a2 = mine ? b2 : a2;
        a3 = mine ? b3 : a3;
    }

    // Circuit on register-resident angles (one item per lane).
    int item = blockBase + myT * 64 + w * 8 + (lane & 7);
    float q0 = 0.f, q1 = 0.f, q2 = 0.f, q3 = 0.f;
    if (item < B) {
        const float inv = 1.f / 36.f;
        float c0, s0, c1, s1, c2, s2, c3, s3;
        __sincosf(a0 * inv, &s0, &c0);
        __sincosf(a1 * inv, &s1, &c1);
        __sincosf(a2 * inv, &s2, &c2);
        __sincosf(a3 * inv, &s3, &c3);

        float t01[9] = { 1.f, c1, s1, c0, c0 * c1, c0 * s1, s0, s0 * c1, s0 * s1 };
        float t23[9] = { 1.f, c3, s3, c2, c2 * c3, c2 * s3, s2, s2 * c3, s2 * s3 };

#pragma unroll
        for (int m = 0; m < 81; m++) {
            float bs = t01[m / 9] * t23[m % 9];
            float4 a = As[m];
            q0 = fmaf(a.x, bs, q0);
            q1 = fmaf(a.y, bs, q1);
            q2 = fmaf(a.z, bs, q2);
            q3 = fmaf(a.w, bs, q3);
        }
        ((float4*)g_q)[item] = make_float4(q0, q1, q2, q3);
    }

    // Per-block partial sums for mean/var.
    float s[8] = { q0, q1, q2, q3, q0 * q0, q1 * q1, q2 * q2, q3 * q3 };
#pragma unroll
    for (int sh = 16; sh; sh >>= 1)
#pragma unroll
        for (int k = 0; k < 8; k++) s[k] += __shfl_xor_sync(0xffffffffu, s[k], sh);
    if (lane == 0) {
#pragma unroll
        for (int k = 0; k < 8; k++) wsum[w][k] = s[k];
    }
    __syncthreads();
    if (tid < 8) {
        float acc = 0.f;
#pragma unroll
        for (int ww = 0; ww < 8; ww++) acc += wsum[ww][tid];
        g_part[blockIdx.x * 8 + tid] = acc;
    }
}

// ---------------------------------------------------------------------------
// Norm: every block redundantly reduces the partials (L2-hot, deterministic,
// identical result per block), then normalizes its slice of q.
// ---------------------------------------------------------------------------
__global__ __launch_bounds__(256)
void norm_kernel(const float* __restrict__ gamma,
                 const float* __restrict__ beta,
                 float* __restrict__ out,
                 int B, int nblocks)
{
    __shared__ double red[8][32];
    __shared__ double tot[8];
    __shared__ float nrm[8];

    int tid = threadIdx.x;
    int k = tid & 7;
    int slice = tid >> 3;
    double acc = 0.0;
    for (int b = slice; b < nblocks; b += 32)
        acc += (double)g_part[b * 8 + k];
    red[k][slice] = acc;
    __syncthreads();
    if (tid < 8) {
        double t = 0.0;
#pragma unroll
        for (int i = 0; i < 32; i++) t += red[tid][i];
        tot[tid] = t;
    }
    __syncthreads();
    if (tid < 4) {
        double mean = tot[tid] / (double)B;
        double var = tot[4 + tid] / (double)B - mean * mean;
        float scale = gamma[tid] * rsqrtf((float)var + 1e-5f);
        nrm[tid] = scale;
        nrm[4 + tid] = beta[tid] - (float)mean * scale;
    }
    __syncthreads();

    int item = blockIdx.x * 256 + tid;
    if (item < B) {
        float4 qv = ((const float4*)g_q)[item];
        float4 o;
        o.x = fmaf(qv.x, nrm[0], nrm[4]);
        o.y = fmaf(qv.y, nrm[1], nrm[5]);
        o.z = fmaf(qv.z, nrm[2], nrm[6]);
        o.w = fmaf(qv.w, nrm[3], nrm[7]);
        ((float4*)out)[item] = o;
    }
}

// ---------------------------------------------------------------------------
extern "C" void kernel_launch(void* const* d_in, const int* in_sizes, int n_in,
                              void* d_out, int out_size)
{
    const float* x     = (const float*)d_in[0];
    const float* W     = (const float*)d_in[1];
    const float* gamma = (const float*)d_in[2];
    const float* beta  = (const float*)d_in[3];
    float* out = (float*)d_out;

    int B = in_sizes[0] / 144;
    int nb = (B + 255) / 256;
    if (nb > MAXBLK) nb = MAXBLK;   // B <= 1M guaranteed by buffers

    setup_kernel<<<1, 1024>>>(W);
    main_kernel<<<nb, 256>>>(x, B);
    norm_kernel<<<nb, 256>>>(gamma, beta, out, B, nb);
}

// round 5
// speedup vs baseline: 1.4484x; 1.1695x over previous
#include <cuda_runtime.h>
#include <math.h>

#define MAXBLK 4096

__device__ __align__(16) float g_Acoef[81 * 4];     // [m][ow]
__device__ __align__(16) float g_q[(1 << 17) * 4];  // q per item
__device__ __align__(16) float g_part[MAXBLK * 8];  // per-block partial sums

struct C2 { float re, im; };

// ---------------------------------------------------------------------------
// Setup: build the 4x81 multilinear coefficient table from weights.
// Latency-optimized: parallel W loads + parallel sincos into smem, then the
// 16 gate-walk threads only read smem (no LDG/MUFU in the dependency chain).
// ---------------------------------------------------------------------------
__global__ void setup_kernel(const float* __restrict__ W)  // [2][4][3]
{
    __shared__ float CS[24][2];     // (cos, sin) of each half-angle
    __shared__ C2 M[16][16];
    __shared__ float G[4][16][16];
    int tid = threadIdx.x;

    // Parallel: one thread per gate angle.
    if (tid < 24) {
        float a = W[tid] * 0.5f;
        float c, s;
        __sincosf(a, &s, &c);
        CS[tid][0] = c;
        CS[tid][1] = s;
    }
    __syncthreads();

    if (tid < 16) {
        int j = tid;
        C2 st[16];
#pragma unroll
        for (int i = 0; i < 16; i++) { st[i].re = (i == j) ? 1.f : 0.f; st[i].im = 0.f; }

#pragma unroll
        for (int l = 0; l < 2; l++) {
#pragma unroll
            for (int w = 0; w < 4; w++) {
                int gi = (l * 4 + w) * 3;
                const int mask = 1 << (3 - w);
                {   // RX
                    float c = CS[gi + 0][0], s = CS[gi + 0][1];
#pragma unroll
                    for (int i = 0; i < 16; i++) {
                        if (i & mask) continue;
                        C2 a = st[i], b = st[i | mask];
                        st[i]        = { c * a.re + s * b.im,  c * a.im - s * b.re };
                        st[i | mask] = { s * a.im + c * b.re, -s * a.re + c * b.im };
                    }
                }
                {   // RY
                    float c = CS[gi + 1][0], s = CS[gi + 1][1];
#pragma unroll
                    for (int i = 0; i < 16; i++) {
                        if (i & mask) continue;
                        C2 a = st[i], b = st[i | mask];
                        st[i]        = { c * a.re - s * b.re, c * a.im - s * b.im };
                        st[i | mask] = { s * a.re + c * b.re, s * a.im + c * b.im };
                    }
                }
                {   // RZ
                    float c = CS[gi + 2][0], s = CS[gi + 2][1];
#pragma unroll
                    for (int i = 0; i < 16; i++) {
                        C2 a = st[i];
                        if (i & mask) st[i] = { c * a.re - s * a.im, c * a.im + s * a.re };
                        else          st[i] = { c * a.re + s * a.im, c * a.im - s * a.re };
                    }
                }
            }
#pragma unroll
            for (int w = 0; w < 4; w++) {     // CNOT ring
                int t = (w + 1) & 3;
                int cm = 1 << (3 - w), tm = 1 << (3 - t);
                C2 tmp[16];
#pragma unroll
                for (int i = 0; i < 16; i++) tmp[i] = st[(i & cm) ? (i ^ tm) : i];
#pragma unroll
                for (int i = 0; i < 16; i++) st[i] = tmp[i];
            }
        }
#pragma unroll
        for (int i = 0; i < 16; i++) M[i][j] = st[i];
    }
    __syncthreads();

    {   // G_ow[j][k] = Re( i^(pc(j)-pc(k)) * sum_i sign_ow(i) conj(M[i][j]) M[i][k] )
        int ow = tid >> 8;
        int j = (tid >> 4) & 15;
        int k = tid & 15;
        float hr = 0.f, hi = 0.f;
#pragma unroll
        for (int i = 0; i < 16; i++) {
            float sgn = ((i >> (3 - ow)) & 1) ? -1.f : 1.f;
            C2 a = M[i][j], b = M[i][k];
            hr += sgn * (a.re * b.re + a.im * b.im);
            hi += sgn * (a.re * b.im - a.im * b.re);
        }
        int ph = (__popc(j) - __popc(k)) & 3;
        float g = (ph == 0) ? hr : (ph == 1) ? -hi : (ph == 2) ? -hr : hi;
        G[ow][j][k] = g;
    }
    __syncthreads();

    if (tid < 324) {   // multilinear coefficients
        int ow = tid / 81;
        int m = tid % 81;
        int md[4] = { m / 27, (m / 9) % 3, (m / 3) % 3, m % 3 };
        float acc = 0.f;
#pragma unroll
        for (int t = 0; t < 16; t++) {
            int j = 0, k = 0;
            float sgn = 1.f;
#pragma unroll
            for (int w = 0; w < 4; w++) {
                int tb = (t >> (3 - w)) & 1;
                int jb, kb;
                if (md[w] == 2) { jb = tb; kb = 1 - tb; }
                else { jb = tb; kb = tb; if (md[w] == 1 && tb == 1) sgn = -sgn; }
                j |= jb << (3 - w);
                k |= kb << (3 - w);
            }
            acc += sgn * G[ow][j][k];
        }
        g_Acoef[m * 4 + ow] = acc * (1.f / 16.f);
    }
}

// ---------------------------------------------------------------------------
// Main: pool (smem transpose, ~1 SHFL/item) + circuit + per-block partials.
// Block handles 256 items as 4 subtiles of 64.
// ---------------------------------------------------------------------------
__global__ __launch_bounds__(256, 3)
void main_kernel(const float* __restrict__ x, int B)
{
    __shared__ float4 tile[64 * 36];      // 36,864 B
    __shared__ float4 As[81];
    __shared__ float wsum[8][8];

    int tid = threadIdx.x;
    int lane = tid & 31;
    int w = tid >> 5;
    if (tid < 81) As[tid] = ((const float4*)g_Acoef)[tid];

    int blockBase = blockIdx.x * 256;
    const float4* x4 = (const float4*)x;
    long totalF4 = (long)B * 36;

    int g = lane >> 2;           // item group within warp-subtile (0..7)
    int q = lane & 3;            // quarter
    int rdBase = (w * 8 + g) * 36 + q * 9;
    int myT = lane >> 3;         // which subtile this lane's item comes from
    int srcLane = (lane & 7) * 4;

    float a0 = 0.f, a1 = 0.f, a2 = 0.f, a3 = 0.f;

#pragma unroll
    for (int t = 0; t < 4; t++) {
        long gBase = (long)(blockBase + t * 64) * 36;
        // Coalesced load of subtile into smem.
#pragma unroll
        for (int k = 0; k < 9; k++) {
            long gi = gBase + tid + k * 256;
            float4 v = make_float4(0.f, 0.f, 0.f, 0.f);
            if (gi < totalF4) v = x4[gi];
            tile[tid + k * 256] = v;
        }
        __syncthreads();

        // Per-thread: sum 9 float4 of quarter q of item (w*8+g).
        float r0 = 0.f, r1 = 0.f;
#pragma unroll
        for (int i = 0; i < 9; i++) {
            float4 v = tile[rdBase + i];
            float sA = v.x + v.y;
            float sB = v.z + v.w;
            if (i % 3 == 0)      r0 += sA + sB;
            else if (i % 3 == 1) { r0 += sA; r1 += sB; }
            else                 r1 += sA + sB;
        }
        __syncthreads();

        // Combine quarters: xor1 merges (q0,q1) and (q2,q3); xor2 swaps halves.
        r0 += __shfl_xor_sync(0xffffffffu, r0, 1);
        r1 += __shfl_xor_sync(0xffffffffu, r1, 1);
        float r2 = __shfl_xor_sync(0xffffffffu, r0, 2);
        float r3 = __shfl_xor_sync(0xffffffffu, r1, 2);

        // Gather: lane owns item (myT subtile, group lane&7) -> src lane 4*(lane&7).
        float b0 = __shfl_sync(0xffffffffu, r0, srcLane);
        float b1 = __shfl_sync(0xffffffffu, r1, srcLane);
        float b2 = __shfl_sync(0xffffffffu, r2, srcLane);
        float b3 = __shfl_sync(0xffffffffu, r3, srcLane);
        bool mine = (myT == t);
        a0 = mine ? b0 : a0;
        a1 = mine ? b1 : a1;
        a2 = mine ? b2 : a2;
        a3 = mine ? b3 : a3;
    }

    // Circuit on register-resident angles (one item per lane).
    int item = blockBase + myT * 64 + w * 8 + (lane & 7);
    float q0 = 0.f, q1 = 0.f, q2 = 0.f, q3 = 0.f;
    if (item < B) {
        const float inv = 1.f / 36.f;
        float c0, s0, c1, s1, c2, s2, c3, s3;
        __sincosf(a0 * inv, &s0, &c0);
        __sincosf(a1 * inv, &s1, &c1);
        __sincosf(a2 * inv, &s2, &c2);
        __sincosf(a3 * inv, &s3, &c3);

        float t01[9] = { 1.f, c1, s1, c0, c0 * c1, c0 * s1, s0, s0 * c1, s0 * s1 };
        float t23[9] = { 1.f, c3, s3, c2, c2 * c3, c2 * s3, s2, s2 * c3, s2 * s3 };

#pragma unroll
        for (int m = 0; m < 81; m++) {
            float bs = t01[m / 9] * t23[m % 9];
            float4 a = As[m];
            q0 = fmaf(a.x, bs, q0);
            q1 = fmaf(a.y, bs, q1);
            q2 = fmaf(a.z, bs, q2);
            q3 = fmaf(a.w, bs, q3);
        }
        ((float4*)g_q)[item] = make_float4(q0, q1, q2, q3);
    }

    // Per-block partial sums for mean/var.
    float s[8] = { q0, q1, q2, q3, q0 * q0, q1 * q1, q2 * q2, q3 * q3 };
#pragma unroll
    for (int sh = 16; sh; sh >>= 1)
#pragma unroll
        for (int k = 0; k < 8; k++) s[k] += __shfl_xor_sync(0xffffffffu, s[k], sh);
    if (lane == 0) {
#pragma unroll
        for (int k = 0; k < 8; k++) wsum[w][k] = s[k];
    }
    __syncthreads();
    if (tid < 8) {
        float acc = 0.f;
#pragma unroll
        for (int ww = 0; ww < 8; ww++) acc += wsum[ww][tid];
        g_part[blockIdx.x * 8 + tid] = acc;
    }
}

// ---------------------------------------------------------------------------
// Norm: every block redundantly reduces the partials (L2-hot, deterministic,
// identical result per block), then normalizes its slice of q.
// ---------------------------------------------------------------------------
__global__ __launch_bounds__(256)
void norm_kernel(const float* __restrict__ gamma,
                 const float* __restrict__ beta,
                 float* __restrict__ out,
                 int B, int nblocks)
{
    __shared__ double red[8][32];
    __shared__ double tot[8];
    __shared__ float nrm[8];

    int tid = threadIdx.x;
    int k = tid & 7;
    int slice = tid >> 3;
    double acc = 0.0;
    for (int b = slice; b < nblocks; b += 32)
        acc += (double)g_part[b * 8 + k];
    red[k][slice] = acc;
    __syncthreads();
    if (tid < 8) {
        double t = 0.0;
#pragma unroll
        for (int i = 0; i < 32; i++) t += red[tid][i];
        tot[tid] = t;
    }
    __syncthreads();
    if (tid < 4) {
        double mean = tot[tid] / (double)B;
        double var = tot[4 + tid] / (double)B - mean * mean;
        float scale = gamma[tid] * rsqrtf((float)var + 1e-5f);
        nrm[tid] = scale;
        nrm[4 + tid] = beta[tid] - (float)mean * scale;
    }
    __syncthreads();

    int item = blockIdx.x * 256 + tid;
    if (item < B) {
        float4 qv = ((const float4*)g_q)[item];
        float4 o;
        o.x = fmaf(qv.x, nrm[0], nrm[4]);
        o.y = fmaf(qv.y, nrm[1], nrm[5]);
        o.z = fmaf(qv.z, nrm[2], nrm[6]);
        o.w = fmaf(qv.w, nrm[3], nrm[7]);
        ((float4*)out)[item] = o;
    }
}

// ---------------------------------------------------------------------------
extern "C" void kernel_launch(void* const* d_in, const int* in_sizes, int n_in,
                              void* d_out, int out_size)
{
    const float* x     = (const float*)d_in[0];
    const float* W     = (const float*)d_in[1];
    const float* gamma = (const float*)d_in[2];
    const float* beta  = (const float*)d_in[3];
    float* out = (float*)d_out;

    int B = in_sizes[0] / 144;
    int nb = (B + 255) / 256;
    if (nb > MAXBLK) nb = MAXBLK;

    setup_kernel<<<1, 1024>>>(W);
    main_kernel<<<nb, 256>>>(x, B);
    norm_kernel<<<nb, 256>>>(gamma, beta, out, B, nb);
}

// round 7
// speedup vs baseline: 1.7244x; 1.1906x over previous
#include <cuda_runtime.h>
#include <math.h>

#define MAXBLK 4096

__device__ __align__(16) float g_Acoef[81 * 4];     // [m][ow]
__device__ __align__(16) float g_q[(1 << 17) * 4];  // q per item
__device__ __align__(16) float g_part[MAXBLK * 8];  // per-block partial sums

// ---------------------------------------------------------------------------
// Setup: lane-parallel. One thread per element (i,j) of the 16x16 circuit
// matrix; gate updates are shfl_xor pair exchanges (chain ~1.1k cycles).
// ---------------------------------------------------------------------------
__device__ __forceinline__ float pick_phase(int ph, float hr, float hi)
{
    return (ph == 0) ? hr : (ph == 1) ? -hi : (ph == 2) ? -hr : hi;
}

__global__ void setup_kernel(const float* __restrict__ W)  // [2][4][3]
{
    __shared__ float CS[24][2];
    __shared__ float Mre[16][16], Mim[16][16];
    __shared__ float G[4][16][16];
    int tid = threadIdx.x;          // 256 threads
    int lane = tid & 31;
    int wrp = tid >> 5;

    if (tid < 24) {
        float c, s;
        __sincosf(W[tid] * 0.5f, &s, &c);
        CS[tid][0] = c;
        CS[tid][1] = s;
    }
    __syncthreads();

    // Thread owns element (i, j): i = lane&15, j = 2*warp + (lane>>4).
    int i = lane & 15;
    int jl = lane >> 4;
    int j = wrp * 2 + jl;
    float re = (i == j) ? 1.f : 0.f;
    float im = 0.f;

#pragma unroll
    for (int l = 0; l < 2; l++) {
#pragma unroll
        for (int g = 0; g < 4; g++) {
            int gi = (l * 4 + g) * 3;
            const int m = 1 << (3 - g);
            float c, s, pre, pim;
            // RX: st' = c*st - i s*partner  (same formula both halves)
            c = CS[gi + 0][0]; s = CS[gi + 0][1];
            pre = __shfl_xor_sync(0xffffffffu, re, m);
            pim = __shfl_xor_sync(0xffffffffu, im, m);
            {
                float nr = fmaf(s, pim, c * re);
                float ni = fmaf(-s, pre, c * im);
                re = nr; im = ni;
            }
            // RY: st' = c*st + (bit? +s : -s)*partner
            c = CS[gi + 1][0]; s = CS[gi + 1][1];
            pre = __shfl_xor_sync(0xffffffffu, re, m);
            pim = __shfl_xor_sync(0xffffffffu, im, m);
            {
                float sg = (i & m) ? s : -s;
                float nr = fmaf(sg, pre, c * re);
                float ni = fmaf(sg, pim, c * im);
                re = nr; im = ni;
            }
            // RZ: multiply by (c -/+ i s)
            c = CS[gi + 2][0]; s = CS[gi + 2][1];
            {
                float tt = (i & m) ? -s : s;
                float nr = fmaf(tt, im, c * re);
                float ni = fmaf(-tt, re, c * im);
                re = nr; im = ni;
            }
        }
        // CNOT ring: st'[i] = st[(i&cm)? i^tm : i]
#pragma unroll
        for (int g = 0; g < 4; g++) {
            int t2 = (g + 1) & 3;
            int cm = 1 << (3 - g), tm = 1 << (3 - t2);
            int src = (((i & cm) ? (i ^ tm) : i) | (jl << 4));
            re = __shfl_sync(0xffffffffu, re, src);
            im = __shfl_sync(0xffffffffu, im, src);
        }
    }
    Mre[i][j] = re;
    Mim[i][j] = im;
    __syncthreads();

    // Stage 2: G_ow[j][k]; compute (tr,ti) terms once, 4 sign accumulations.
    {
        int j2 = tid >> 4, k2 = tid & 15;
        float hr0 = 0, hr1 = 0, hr2 = 0, hr3 = 0;
        float hi0 = 0, hi1 = 0, hi2 = 0, hi3 = 0;
#pragma unroll
        for (int i2 = 0; i2 < 16; i2++) {
            float ar = Mre[i2][j2], ai = Mim[i2][j2];
            float br = Mre[i2][k2], bi = Mim[i2][k2];
            float tr = ar * br + ai * bi;
            float ti = ar * bi - ai * br;
            if (i2 & 8) { hr0 -= tr; hi0 -= ti; } else { hr0 += tr; hi0 += ti; }
            if (i2 & 4) { hr1 -= tr; hi1 -= ti; } else { hr1 += tr; hi1 += ti; }
            if (i2 & 2) { hr2 -= tr; hi2 -= ti; } else { hr2 += tr; hi2 += ti; }
            if (i2 & 1) { hr3 -= tr; hi3 -= ti; } else { hr3 += tr; hi3 += ti; }
        }
        int ph = (__popc(j2) - __popc(k2)) & 3;
        G[0][j2][k2] = pick_phase(ph, hr0, hi0);
        G[1][j2][k2] = pick_phase(ph, hr1, hi1);
        G[2][j2][k2] = pick_phase(ph, hr2, hi2);
        G[3][j2][k2] = pick_phase(ph, hr3, hi3);
    }
    __syncthreads();

    // Stage 3: multilinear coefficients (324 entries, 256 threads loop).
    for (int idx = tid; idx < 324; idx += 256) {
        int ow = idx / 81;
        int m = idx % 81;
        int md[4] = { m / 27, (m / 9) % 3, (m / 3) % 3, m % 3 };
        float acc = 0.f;
#pragma unroll
        for (int t = 0; t < 16; t++) {
            int jj = 0, kk = 0;
            float sgn = 1.f;
#pragma unroll
            for (int w = 0; w < 4; w++) {
                int tb = (t >> (3 - w)) & 1;
                int jb, kb;
                if (md[w] == 2) { jb = tb; kb = 1 - tb; }
                else { jb = tb; kb = tb; if (md[w] == 1 && tb == 1) sgn = -sgn; }
                jj |= jb << (3 - w);
                kk |= kb << (3 - w);
            }
            acc += sgn * G[ow][jj][kk];
        }
        g_Acoef[m * 4 + ow] = acc * (1.f / 16.f);
    }
}

// ---------------------------------------------------------------------------
// Main: double-buffered pooling (float2-compressed smem, 1 sync/subtile,
// loads always in flight) + circuit + per-block partials.
// ---------------------------------------------------------------------------
__global__ __launch_bounds__(256, 3)
void main_kernel(const float* __restrict__ x, int B)
{
    __shared__ float2 tile[2][64 * 36];   // 2 x 18,432 B
    __shared__ float4 As[81];
    __shared__ float wsum[8][8];

    int tid = threadIdx.x;
    int lane = tid & 31;
    int w = tid >> 5;
    if (tid < 81) As[tid] = ((const float4*)g_Acoef)[tid];

    int blockBase = blockIdx.x * 256;
    const float4* x4 = (const float4*)x;
    long totalF4 = (long)B * 36;

    int g = lane >> 2;            // item group within warp-subtile (0..7)
    int q = lane & 3;             // quarter
    int rdBase = (w * 8 + g) * 36 + q * 9;
    int myT = lane >> 3;          // which subtile this lane's item comes from
    int srcLane = (lane & 7) * 4;

    float sx[9], sz[9];

    // Prologue: load + compress subtile 0.
    {
        long gBase = (long)blockBase * 36;
#pragma unroll
        for (int k = 0; k < 9; k++) {
            long gi = gBase + tid + k * 256;
            float4 v = make_float4(0.f, 0.f, 0.f, 0.f);
            if (gi < totalF4) v = x4[gi];
            sx[k] = v.x + v.y;
            sz[k] = v.z + v.w;
        }
#pragma unroll
        for (int k = 0; k < 9; k++)
            tile[0][tid + k * 256] = make_float2(sx[k], sz[k]);
    }

    float a0 = 0.f, a1 = 0.f, a2 = 0.f, a3 = 0.f;

#pragma unroll
    for (int t = 0; t < 4; t++) {
        __syncthreads();   // buffer t ready

        // Issue next subtile's loads (stay in flight during compute).
        if (t < 3) {
            long gBase = (long)(blockBase + (t + 1) * 64) * 36;
#pragma unroll
            for (int k = 0; k < 9; k++) {
                long gi = gBase + tid + k * 256;
                float4 v = make_float4(0.f, 0.f, 0.f, 0.f);
                if (gi < totalF4) v = x4[gi];
                sx[k] = v.x + v.y;
                sz[k] = v.z + v.w;
            }
        }

        // Pooling compute from buffer t.
        float r0 = 0.f, r1 = 0.f;
        const float2* tp = tile[t & 1] + rdBase;
#pragma unroll
        for (int i = 0; i < 9; i++) {
            float2 v = tp[i];
            if (i % 3 == 0)      r0 += v.x + v.y;
            else if (i % 3 == 1) { r0 += v.x; r1 += v.y; }
            else                 r1 += v.x + v.y;
        }
        r0 += __shfl_xor_sync(0xffffffffu, r0, 1);
        r1 += __shfl_xor_sync(0xffffffffu, r1, 1);
        float r2 = __shfl_xor_sync(0xffffffffu, r0, 2);
        float r3 = __shfl_xor_sync(0xffffffffu, r1, 2);

        float b0 = __shfl_sync(0xffffffffu, r0, srcLane);
        float b1 = __shfl_sync(0xffffffffu, r1, srcLane);
        float b2 = __shfl_sync(0xffffffffu, r2, srcLane);
        float b3 = __shfl_sync(0xffffffffu, r3, srcLane);
        bool mine = (myT == t);
        a0 = mine ? b0 : a0;
        a1 = mine ? b1 : a1;
        a2 = mine ? b2 : a2;
        a3 = mine ? b3 : a3;

        // Store staged data into the other buffer.
        if (t < 3) {
#pragma unroll
            for (int k = 0; k < 9; k++)
                tile[(t + 1) & 1][tid + k * 256] = make_float2(sx[k], sz[k]);
        }
    }

    // Circuit on register-resident angles (one item per lane).
    int item = blockBase + myT * 64 + w * 8 + (lane & 7);
    float q0 = 0.f, q1 = 0.f, q2 = 0.f, q3 = 0.f;
    if (item < B) {
        const float inv = 1.f / 36.f;
        float c0, s0, c1, s1, c2, s2, c3, s3;
        __sincosf(a0 * inv, &s0, &c0);
        __sincosf(a1 * inv, &s1, &c1);
        __sincosf(a2 * inv, &s2, &c2);
        __sincosf(a3 * inv, &s3, &c3);

        float t01[9] = { 1.f, c1, s1, c0, c0 * c1, c0 * s1, s0, s0 * c1, s0 * s1 };
        float t23[9] = { 1.f, c3, s3, c2, c2 * c3, c2 * s3, s2, s2 * c3, s2 * s3 };

#pragma unroll
        for (int m = 0; m < 81; m++) {
            float bs = t01[m / 9] * t23[m % 9];
            float4 a = As[m];
            q0 = fmaf(a.x, bs, q0);
            q1 = fmaf(a.y, bs, q1);
            q2 = fmaf(a.z, bs, q2);
            q3 = fmaf(a.w, bs, q3);
        }
        ((float4*)g_q)[item] = make_float4(q0, q1, q2, q3);
    }

    // Per-block partial sums for mean/var.
    float s[8] = { q0, q1, q2, q3, q0 * q0, q1 * q1, q2 * q2, q3 * q3 };
#pragma unroll
    for (int sh = 16; sh; sh >>= 1)
#pragma unroll
        for (int k = 0; k < 8; k++) s[k] += __shfl_xor_sync(0xffffffffu, s[k], sh);
    if (lane == 0) {
#pragma unroll
        for (int k = 0; k < 8; k++) wsum[w][k] = s[k];
    }
    __syncthreads();
    if (tid < 8) {
        float acc = 0.f;
#pragma unroll
        for (int ww = 0; ww < 8; ww++) acc += wsum[ww][tid];
        g_part[blockIdx.x * 8 + tid] = acc;
    }
}

// ---------------------------------------------------------------------------
// Norm: every block redundantly reduces the partials (L2-hot, deterministic),
// then normalizes its slice of q.
// ---------------------------------------------------------------------------
__global__ __launch_bounds__(256)
void norm_kernel(const float* __restrict__ gamma,
                 const float* __restrict__ beta,
                 float* __restrict__ out,
                 int B, int nblocks)
{
    __shared__ double red[8][32];
    __shared__ double tot[8];
    __shared__ float nrm[8];

    int tid = threadIdx.x;
    int k = tid & 7;
    int slice = tid >> 3;
    double acc = 0.0;
    for (int b = slice; b < nblocks; b += 32)
        acc += (double)g_part[b * 8 + k];
    red[k][slice] = acc;
    __syncthreads();
    if (tid < 8) {
        double t = 0.0;
#pragma unroll
        for (int i = 0; i < 32; i++) t += red[tid][i];
        tot[tid] = t;
    }
    __syncthreads();
    if (tid < 4) {
        double mean = tot[tid] / (double)B;
        double var = tot[4 + tid] / (double)B - mean * mean;
        float scale = gamma[tid] * rsqrtf((float)var + 1e-5f);
        nrm[tid] = scale;
        nrm[4 + tid] = beta[tid] - (float)mean * scale;
    }
    __syncthreads();

    int item = blockIdx.x * 256 + tid;
    if (item < B) {
        float4 qv = ((const float4*)g_q)[item];
        float4 o;
        o.x = fmaf(qv.x, nrm[0], nrm[4]);
        o.y = fmaf(qv.y, nrm[1], nrm[5]);
        o.z = fmaf(qv.z, nrm[2], nrm[6]);
        o.w = fmaf(qv.w, nrm[3], nrm[7]);
        ((float4*)out)[item] = o;
    }
}

// ---------------------------------------------------------------------------
extern "C" void kernel_launch(void* const* d_in, const int* in_sizes, int n_in,
                              void* d_out, int out_size)
{
    const float* x     = (const float*)d_in[0];
    const float* W     = (const float*)d_in[1];
    const float* gamma = (const float*)d_in[2];
    const float* beta  = (const float*)d_in[3];
    float* out = (float*)d_out;

    int B = in_sizes[0] / 144;
    int nb = (B + 255) / 256;
    if (nb > MAXBLK) nb = MAXBLK;

    setup_kernel<<<1, 256>>>(W);
    main_kernel<<<nb, 256>>>(x, B);
    norm_kernel<<<nb, 256>>>(gamma, beta, out, B, nb);
}

// round 8
// speedup vs baseline: 1.9870x; 1.1523x over previous
#include <cuda_runtime.h>
#include <math.h>

#define NB_MAX 296

__device__ __align__(16) float g_Acoef[81 * 4];
__device__ __align__(16) float g_part[NB_MAX * 8];
__device__ __align__(16) float g_norm[8];
__device__ int g_ticket;                 // monotonic across launches
__device__ int g_arrive;                 // monotonic across launches
__device__ volatile int g_acoef_flag;    // released as gen+1
__device__ volatile int g_norm_flag;     // released as gen+1

__device__ __forceinline__ float pick_phase(int ph, float hr, float hi)
{
    return (ph == 0) ? hr : (ph == 1) ? -hi : (ph == 2) ? -hr : hi;
}

__device__ __forceinline__ void circuit_eval(const float4* __restrict__ As,
                                             float a0, float a1, float a2, float a3,
                                             float& q0, float& q1, float& q2, float& q3)
{
    const float inv = 1.f / 36.f;
    float c0, s0, c1, s1, c2, s2, c3, s3;
    __sincosf(a0 * inv, &s0, &c0);
    __sincosf(a1 * inv, &s1, &c1);
    __sincosf(a2 * inv, &s2, &c2);
    __sincosf(a3 * inv, &s3, &c3);
    float t01[9] = { 1.f, c1, s1, c0, c0 * c1, c0 * s1, s0, s0 * c1, s0 * s1 };
    float t23[9] = { 1.f, c3, s3, c2, c2 * c3, c2 * s3, s2, s2 * c3, s2 * s3 };
#pragma unroll
    for (int m = 0; m < 81; m++) {
        float bs = t01[m / 9] * t23[m % 9];
        float4 a = As[m];
        q0 = fmaf(a.x, bs, q0);
        q1 = fmaf(a.y, bs, q1);
        q2 = fmaf(a.z, bs, q2);
        q3 = fmaf(a.w, bs, q3);
    }
}

// ---------------------------------------------------------------------------
// Single fused kernel: setup(block0) + pool + circuit + mean/var + norm + out.
// ---------------------------------------------------------------------------
__global__ __launch_bounds__(256, 2)
void fused_kernel(const float* __restrict__ x,
                  const float* __restrict__ W,
                  const float* __restrict__ gamma,
                  const float* __restrict__ beta,
                  float* __restrict__ out,
                  int B, int nb, int nChunks)
{
    __shared__ float2 tile[2][64 * 36];   // 36,864 B double buffer
    __shared__ float4 As[81];
    __shared__ float wsum[8][8];
    __shared__ int shGen;
    __shared__ int shLast;
    __shared__ union {
        struct {
            float CS[24][2];
            float Mre[16][16];
            float Mim[16][16];
            float G[4][16][16];
        } su;                              // setup phase (block 0)
        struct {
            double red[8][32];
            double tot[8];
        } ru;                              // final reduce phase (last block)
    } U;

    int tid = threadIdx.x;
    int lane = tid & 31;
    int w = tid >> 5;

    if (tid == 0) shGen = atomicAdd(&g_ticket, 1) / nb;
    __syncthreads();
    int gen = shGen;

    // ---- Block 0: build the 4x81 coefficient table (lane-parallel) ----
    if (blockIdx.x == 0) {
        if (tid < 24) {
            float c, s;
            __sincosf(W[tid] * 0.5f, &s, &c);
            U.su.CS[tid][0] = c;
            U.su.CS[tid][1] = s;
        }
        __syncthreads();
        {
            int i = lane & 15;
            int jl = lane >> 4;
            int j = w * 2 + jl;
            float re = (i == j) ? 1.f : 0.f;
            float im = 0.f;
#pragma unroll
            for (int l = 0; l < 2; l++) {
#pragma unroll
                for (int g2 = 0; g2 < 4; g2++) {
                    int gi = (l * 4 + g2) * 3;
                    const int m = 1 << (3 - g2);
                    float c, s, pre, pim;
                    // RX
                    c = U.su.CS[gi + 0][0]; s = U.su.CS[gi + 0][1];
                    pre = __shfl_xor_sync(0xffffffffu, re, m);
                    pim = __shfl_xor_sync(0xffffffffu, im, m);
                    {
                        float nr = fmaf(s, pim, c * re);
                        float ni = fmaf(-s, pre, c * im);
                        re = nr; im = ni;
                    }
                    // RY
                    c = U.su.CS[gi + 1][0]; s = U.su.CS[gi + 1][1];
                    pre = __shfl_xor_sync(0xffffffffu, re, m);
                    pim = __shfl_xor_sync(0xffffffffu, im, m);
                    {
                        float sg = (i & m) ? s : -s;
                        float nr = fmaf(sg, pre, c * re);
                        float ni = fmaf(sg, pim, c * im);
                        re = nr; im = ni;
                    }
                    // RZ
                    c = U.su.CS[gi + 2][0]; s = U.su.CS[gi + 2][1];
                    {
                        float tt = (i & m) ? -s : s;
                        float nr = fmaf(tt, im, c * re);
                        float ni = fmaf(-tt, re, c * im);
                        re = nr; im = ni;
                    }
                }
#pragma unroll
                for (int g2 = 0; g2 < 4; g2++) {
                    int t2 = (g2 + 1) & 3;
                    int cm = 1 << (3 - g2), tm = 1 << (3 - t2);
                    int src = (((i & cm) ? (i ^ tm) : i) | (jl << 4));
                    re = __shfl_sync(0xffffffffu, re, src);
                    im = __shfl_sync(0xffffffffu, im, src);
                }
            }
            U.su.Mre[i][j] = re;
            U.su.Mim[i][j] = im;
        }
        __syncthreads();
        {
            int j2 = tid >> 4, k2 = tid & 15;
            float hr0 = 0, hr1 = 0, hr2 = 0, hr3 = 0;
            float hi0 = 0, hi1 = 0, hi2 = 0, hi3 = 0;
#pragma unroll
            for (int i2 = 0; i2 < 16; i2++) {
                float ar = U.su.Mre[i2][j2], ai = U.su.Mim[i2][j2];
                float br = U.su.Mre[i2][k2], bi = U.su.Mim[i2][k2];
                float tr = ar * br + ai * bi;
                float ti = ar * bi - ai * br;
                if (i2 & 8) { hr0 -= tr; hi0 -= ti; } else { hr0 += tr; hi0 += ti; }
                if (i2 & 4) { hr1 -= tr; hi1 -= ti; } else { hr1 += tr; hi1 += ti; }
                if (i2 & 2) { hr2 -= tr; hi2 -= ti; } else { hr2 += tr; hi2 += ti; }
                if (i2 & 1) { hr3 -= tr; hi3 -= ti; } else { hr3 += tr; hi3 += ti; }
            }
            int ph = (__popc(j2) - __popc(k2)) & 3;
            U.su.G[0][j2][k2] = pick_phase(ph, hr0, hi0);
            U.su.G[1][j2][k2] = pick_phase(ph, hr1, hi1);
            U.su.G[2][j2][k2] = pick_phase(ph, hr2, hi2);
            U.su.G[3][j2][k2] = pick_phase(ph, hr3, hi3);
        }
        __syncthreads();
        for (int idx = tid; idx < 324; idx += 256) {
            int ow = idx / 81;
            int m = idx % 81;
            int md[4] = { m / 27, (m / 9) % 3, (m / 3) % 3, m % 3 };
            float acc = 0.f;
#pragma unroll
            for (int t = 0; t < 16; t++) {
                int jj = 0, kk = 0;
                float sgn = 1.f;
#pragma unroll
                for (int w2 = 0; w2 < 4; w2++) {
                    int tb = (t >> (3 - w2)) & 1;
                    int jb, kb;
                    if (md[w2] == 2) { jb = tb; kb = 1 - tb; }
                    else { jb = tb; kb = tb; if (md[w2] == 1 && tb == 1) sgn = -sgn; }
                    jj |= jb << (3 - w2);
                    kk |= kb << (3 - w2);
                }
                acc += sgn * U.su.G[ow][jj][kk];
            }
            g_Acoef[m * 4 + ow] = acc * (1.f / 16.f);
            __threadfence();
        }
        __syncthreads();
        if (tid == 0) g_acoef_flag = gen + 1;
    }

    // ---- Tile assignment: block 0 gets lightest load (setup straggler) ----
    int tiles0 = blockIdx.x;
    int rev = nb - 1 - blockIdx.x;
    int tiles1 = (nb + rev < nChunks) ? (nb + rev) : -1;
    int nt = (tiles1 >= 0) ? 2 : 1;

    // ---- Pooling: double-buffered, 1 sync/subtile ----
    const float4* x4 = (const float4*)x;
    long totalF4 = (long)B * 36;
    int g = lane >> 2;
    int q = lane & 3;
    int rdBase = (w * 8 + g) * 36 + q * 9;
    int myT = lane >> 3;
    int srcLane = (lane & 7) * 4;

    float A00 = 0, A01 = 0, A02 = 0, A03 = 0;   // tile-0 angles (x36)
    float A10 = 0, A11 = 0, A12 = 0, A13 = 0;   // tile-1 angles (x36)
    float sx[9], sz[9];

    {   // prologue: subtile 0 of tile 0
        long gBase = (long)tiles0 * 9216;
#pragma unroll
        for (int k = 0; k < 9; k++) {
            long gi = gBase + tid + k * 256;
            float4 v = make_float4(0.f, 0.f, 0.f, 0.f);
            if (gi < totalF4) v = x4[gi];
            sx[k] = v.x + v.y;
            sz[k] = v.z + v.w;
        }
#pragma unroll
        for (int k = 0; k < 9; k++)
            tile[0][tid + k * 256] = make_float2(sx[k], sz[k]);
    }

    int totalSub = nt * 4;
    for (int s = 0; s < totalSub; s++) {
        __syncthreads();
        bool hasNext = (s + 1 < totalSub);
        if (hasNext) {
            int tsel = ((s + 1) >> 2) ? tiles1 : tiles0;
            long gBase = (long)tsel * 9216 + ((s + 1) & 3) * 2304;
#pragma unroll
            for (int k = 0; k < 9; k++) {
                long gi = gBase + tid + k * 256;
                float4 v = make_float4(0.f, 0.f, 0.f, 0.f);
                if (gi < totalF4) v = x4[gi];
                sx[k] = v.x + v.y;
                sz[k] = v.z + v.w;
            }
        }

        const float2* tp = tile[s & 1] + rdBase;
        float r0 = 0.f, r1 = 0.f;
#pragma unroll
        for (int i = 0; i < 9; i++) {
            float2 v = tp[i];
            if (i % 3 == 0)      r0 += v.x + v.y;
            else if (i % 3 == 1) { r0 += v.x; r1 += v.y; }
            else                 r1 += v.x + v.y;
        }
        r0 += __shfl_xor_sync(0xffffffffu, r0, 1);
        r1 += __shfl_xor_sync(0xffffffffu, r1, 1);
        float r2 = __shfl_xor_sync(0xffffffffu, r0, 2);
        float r3 = __shfl_xor_sync(0xffffffffu, r1, 2);

        float b0 = __shfl_sync(0xffffffffu, r0, srcLane);
        float b1 = __shfl_sync(0xffffffffu, r1, srcLane);
        float b2 = __shfl_sync(0xffffffffu, r2, srcLane);
        float b3 = __shfl_sync(0xffffffffu, r3, srcLane);
        bool mine = ((s & 3) == myT);
        if ((s >> 2) == 0) {
            A00 = mine ? b0 : A00;  A01 = mine ? b1 : A01;
            A02 = mine ? b2 : A02;  A03 = mine ? b3 : A03;
        } else {
            A10 = mine ? b0 : A10;  A11 = mine ? b1 : A11;
            A12 = mine ? b2 : A12;  A13 = mine ? b3 : A13;
        }

        if (hasNext) {
#pragma unroll
            for (int k = 0; k < 9; k++)
                tile[(s + 1) & 1][tid + k * 256] = make_float2(sx[k], sz[k]);
        }
    }

    // ---- Wait for coefficients (long done by now), load As ----
    if (blockIdx.x != 0) {
        if (tid == 0) {
            while (g_acoef_flag < gen + 1) __nanosleep(32);
        }
        __syncthreads();
        __threadfence();
    }
    if (tid < 81) As[tid] = __ldcg(((const float4*)g_Acoef) + tid);
    __syncthreads();

    // ---- Circuit (register-resident) + partial sums ----
    int itemLocal = myT * 64 + w * 8 + (lane & 7);
    float q00 = 0, q01 = 0, q02 = 0, q03 = 0;
    float q10 = 0, q11 = 0, q12 = 0, q13 = 0;
    {
        int item = tiles0 * 256 + itemLocal;
        if (item < B) circuit_eval(As, A00, A01, A02, A03, q00, q01, q02, q03);
    }
    if (nt == 2) {
        int item = tiles1 * 256 + itemLocal;
        if (item < B) circuit_eval(As, A10, A11, A12, A13, q10, q11, q12, q13);
    }

    float s8[8] = { q00 + q10, q01 + q11, q02 + q12, q03 + q13,
                    q00 * q00 + q10 * q10, q01 * q01 + q11 * q11,
                    q02 * q02 + q12 * q12, q03 * q03 + q13 * q13 };
#pragma unroll
    for (int sh = 16; sh; sh >>= 1)
#pragma unroll
        for (int k = 0; k < 8; k++) s8[k] += __shfl_xor_sync(0xffffffffu, s8[k], sh);
    if (lane == 0) {
#pragma unroll
        for (int k = 0; k < 8; k++) wsum[w][k] = s8[k];
    }
    __syncthreads();
    if (tid < 8) {
        float acc = 0.f;
#pragma unroll
        for (int ww = 0; ww < 8; ww++) acc += wsum[ww][tid];
        g_part[blockIdx.x * 8 + tid] = acc;
        __threadfence();
    }
    __syncthreads();

    // ---- Arrival; last block computes norm params ----
    if (tid == 0) {
        int pos = atomicAdd(&g_arrive, 1);
        shLast = ((pos % nb) == nb - 1);
    }
    __syncthreads();

    if (shLast) {
        __threadfence();
        int k = tid & 7;
        int slice = tid >> 3;
        double acc = 0.0;
        for (int b = slice; b < nb; b += 32)
            acc += (double)g_part[b * 8 + k];
        U.ru.red[k][slice] = acc;
        __syncthreads();
        if (tid < 8) {
            double t = 0.0;
#pragma unroll
            for (int i = 0; i < 32; i++) t += U.ru.red[tid][i];
            U.ru.tot[tid] = t;
        }
        __syncthreads();
        if (tid < 4) {
            double mean = U.ru.tot[tid] / (double)B;
            double var = U.ru.tot[4 + tid] / (double)B - mean * mean;
            float scale = gamma[tid] * rsqrtf((float)var + 1e-5f);
            g_norm[tid] = scale;
            g_norm[4 + tid] = beta[tid] - (float)mean * scale;
            __threadfence();
        }
        __syncthreads();
        if (tid == 0) g_norm_flag = gen + 1;
    }

    // ---- Wait for norm params, apply to register q, write out ----
    if (tid == 0) {
        while (g_norm_flag < gen + 1) __nanosleep(32);
    }
    __syncthreads();
    __threadfence();

    float sc0 = __ldcg(&g_norm[0]), sc1 = __ldcg(&g_norm[1]);
    float sc2 = __ldcg(&g_norm[2]), sc3 = __ldcg(&g_norm[3]);
    float bs0 = __ldcg(&g_norm[4]), bs1 = __ldcg(&g_norm[5]);
    float bs2 = __ldcg(&g_norm[6]), bs3 = __ldcg(&g_norm[7]);

    {
        int item = tiles0 * 256 + itemLocal;
        if (item < B) {
            float4 o;
            o.x = fmaf(q00, sc0, bs0);
            o.y = fmaf(q01, sc1, bs1);
            o.z = fmaf(q02, sc2, bs2);
            o.w = fmaf(q03, sc3, bs3);
            ((float4*)out)[item] = o;
        }
    }
    if (nt == 2) {
        int item = tiles1 * 256 + itemLocal;
        if (item < B) {
            float4 o;
            o.x = fmaf(q10, sc0, bs0);
            o.y = fmaf(q11, sc1, bs1);
            o.z = fmaf(q12, sc2, bs2);
            o.w = fmaf(q13, sc3, bs3);
            ((float4*)out)[item] = o;
        }
    }
}

// ---------------------------------------------------------------------------
extern "C" void kernel_launch(void* const* d_in, const int* in_sizes, int n_in,
                              void* d_out, int out_size)
{
    const float* x     = (const float*)d_in[0];
    const float* W     = (const float*)d_in[1];
    const float* gamma = (const float*)d_in[2];
    const float* beta  = (const float*)d_in[3];
    float* out = (float*)d_out;

    int B = in_sizes[0] / 144;
    int nChunks = (B + 255) / 256;
    int nb = (nChunks < NB_MAX) ? nChunks : NB_MAX;

    fused_kernel<<<nb, 256>>>(x, W, gamma, beta, out, B, nb, nChunks);
}